// round 14
// baseline (speedup 1.0000x reference)
#include <cuda_runtime.h>
#include <cuda_fp16.h>
#include <math.h>
#include <stdint.h>

#define Bn 8
#define C1 256
#define CH 128
#define C2 256
#define Hh 80
#define Ww 80
#define HW 6400
#define NT 9
#define KT 1152
#define OC 27
#define NCHK 36   /* k3/k2 K chunks of 32, k' = n*128 + c */
#define NCHK1 8   /* k1: K=256 */
#define NCHK4 4   /* k4: K=128 */

// -------- scratch --------
__device__ float g_y1[Bn*CH*HW];     // post cv1+bn1+silu, [b][c][hw]
__device__ float g_z[Bn*CH*HW];      // post dcn+bn2+silu, [b][c][hw]
__device__ float g_off[Bn*18*HW];
__device__ float g_mask[Bn*NT*HW];
__device__ uint32_t g_dcnH[NCHK*2048];   // fp16x2 weights (hi only)
__device__ uint32_t g_w1H[NCHK1*2048];
__device__ uint32_t g_w2H[2*NCHK4*2048];
__device__ uint32_t g_owH[NCHK*512];
__device__ float g_s1[CH], g_t1[CH], g_s2[CH], g_t2[CH], g_s3[C2], g_t3[C2];

__device__ __forceinline__ float silu_f(float v) { return v / (1.f + __expf(-v)); }

__device__ __forceinline__ uint32_t pack2h(float a, float b) {
    __half2 t = __floats2half2_rn(a, b);
    return *(uint32_t*)&t;
}
__device__ __forceinline__ uint32_t smem_u32(const void* p) {
    uint32_t a; asm("{ .reg .u64 t; cvta.to.shared.u64 t, %1; cvt.u32.u64 %0, t; }" : "=r"(a) : "l"(p));
    return a;
}
#define LDM_X4(r0,r1,r2,r3,addr) \
    asm volatile("ldmatrix.sync.aligned.m8n8.x4.shared.b16 {%0,%1,%2,%3}, [%4];" \
        : "=r"(r0),"=r"(r1),"=r"(r2),"=r"(r3) : "r"(addr))

__device__ __forceinline__ void mma_f16(float* c, const uint32_t* a, const uint32_t* b) {
    asm volatile(
        "mma.sync.aligned.m16n8k16.row.col.f32.f16.f16.f32 "
        "{%0,%1,%2,%3}, {%4,%5,%6,%7}, {%8,%9}, {%0,%1,%2,%3};"
        : "+f"(c[0]), "+f"(c[1]), "+f"(c[2]), "+f"(c[3])
        : "r"(a[0]), "r"(a[1]), "r"(a[2]), "r"(a[3]), "r"(b[0]), "r"(b[1]));
}
// B data split: hi + lo fp16
__device__ __forceinline__ void split_pack_h(float w0, float w1, uint32_t* hi, uint32_t* lo) {
    float h0 = __half2float(__float2half_rn(w0));
    float h1 = __half2float(__float2half_rn(w1));
    *hi = pack2h(h0, h1);
    *lo = pack2h(w0 - h0, w1 - h1);
}
__device__ __forceinline__ void cpasync16(uint32_t dst, const void* src) {
    asm volatile("cp.async.cg.shared.global [%0], [%1], 16;" :: "r"(dst), "l"(src) : "memory");
}
__device__ __forceinline__ void split_sts16(const float* acc, uint32_t dh, uint32_t dl) {
    #pragma unroll
    for (int q = 0; q < 2; q++) {
        uint32_t ph[4], pl[4];
        #pragma unroll
        for (int jj = 0; jj < 4; jj++)
            split_pack_h(acc[q*8 + jj*2], acc[q*8 + jj*2 + 1], &ph[jj], &pl[jj]);
        asm volatile("st.shared.v4.b32 [%0], {%1,%2,%3,%4};" ::
            "r"(dh + q*16), "r"(ph[0]), "r"(ph[1]), "r"(ph[2]), "r"(ph[3]));
        asm volatile("st.shared.v4.b32 [%0], {%1,%2,%3,%4};" ::
            "r"(dl + q*16), "r"(pl[0]), "r"(pl[1]), "r"(pl[2]), "r"(pl[3]));
    }
}
#define BAR_SYNC(id)   asm volatile("bar.sync %0, 512;"   :: "r"(id) : "memory")
#define BAR_ARRIVE(id) asm volatile("bar.arrive %0, 512;" :: "r"(id) : "memory")

// high-MLP bilinear gather for 16 channels
__device__ __forceinline__ void gather16(const float* pb, int i0, int i1, int i2, int i3,
                                         float4 wv, float* acc) {
    float l0[16], l1[16];
    #pragma unroll
    for (int jj = 0; jj < 16; jj++) l0[jj] = __ldg(pb + (size_t)jj*HW + i0);
    #pragma unroll
    for (int jj = 0; jj < 16; jj++) l1[jj] = __ldg(pb + (size_t)jj*HW + i1);
    #pragma unroll
    for (int jj = 0; jj < 16; jj++) acc[jj] = wv.x*l0[jj] + wv.y*l1[jj];
    #pragma unroll
    for (int jj = 0; jj < 16; jj++) l0[jj] = __ldg(pb + (size_t)jj*HW + i2);
    #pragma unroll
    for (int jj = 0; jj < 16; jj++) l1[jj] = __ldg(pb + (size_t)jj*HW + i3);
    #pragma unroll
    for (int jj = 0; jj < 16; jj++) acc[jj] += wv.z*l0[jj] + wv.w*l1[jj];
}

// -------- prep --------
__global__ void prep_kernel(const float* __restrict__ cv1w,
                            const float* __restrict__ bn1g, const float* __restrict__ bn1b,
                            const float* __restrict__ bn1m, const float* __restrict__ bn1v,
                            const float* __restrict__ offw, const float* __restrict__ dcnw,
                            const float* __restrict__ bn2g, const float* __restrict__ bn2b,
                            const float* __restrict__ bn2m, const float* __restrict__ bn2v,
                            const float* __restrict__ cv2w,
                            const float* __restrict__ bn3g, const float* __restrict__ bn3b,
                            const float* __restrict__ bn3m, const float* __restrict__ bn3v) {
    int idx0 = blockIdx.x * blockDim.x + threadIdx.x;
    int stride = gridDim.x * blockDim.x;
    for (int i = idx0; i < NCHK*2048; i += stride) {
        int ch = i >> 11, r = i & 2047;
        int o = r >> 4, kp = r & 15;
        int kk = ch*32 + kp*2;
        int n = kk >> 7, c = kk & 127;
        g_dcnH[i] = pack2h(dcnw[o*KT + c*9 + n], dcnw[o*KT + (c+1)*9 + n]);
    }
    for (int i = idx0; i < NCHK1*2048; i += stride) {
        int ch = i >> 11, r = i & 2047;
        int o = r >> 4, kp = r & 15;
        int c = ch*32 + kp*2;
        g_w1H[i] = pack2h(cv1w[o*C1 + c], cv1w[o*C1 + c + 1]);
    }
    for (int i = idx0; i < 2*NCHK4*2048; i += stride) {
        int z = i >> 13, r1 = i & 8191;
        int ch = r1 >> 11, r = r1 & 2047;
        int o = r >> 4, kp = r & 15;
        int c = ch*32 + kp*2;
        g_w2H[i] = pack2h(cv2w[(z*128+o)*CH + c], cv2w[(z*128+o)*CH + c + 1]);
    }
    for (int i = idx0; i < NCHK*512; i += stride) {
        int ch = i >> 9, r = i & 511;
        int o = r >> 4, kp = r & 15;
        int kk = ch*32 + kp*2;
        int n = kk >> 7, c = kk & 127;
        float w0 = (o < OC) ? offw[o*KT + c*9 + n] : 0.f;
        float w1 = (o < OC) ? offw[o*KT + (c+1)*9 + n] : 0.f;
        g_owH[i] = pack2h(w0, w1);
    }
    for (int i = idx0; i < CH; i += stride) {
        float s = bn1g[i] * rsqrtf(bn1v[i] + 1e-5f);
        g_s1[i] = s; g_t1[i] = bn1b[i] - bn1m[i]*s;
        float s2 = bn2g[i] * rsqrtf(bn2v[i] + 1e-5f);
        g_s2[i] = s2; g_t2[i] = bn2b[i] - bn2m[i]*s2;
    }
    for (int i = idx0; i < C2; i += stride) {
        float s = bn3g[i] * rsqrtf(bn3v[i] + 1e-5f);
        g_s3[i] = s; g_t3[i] = bn3b[i] - bn3m[i]*s;
    }
}

// ======== k1: cv1 (1x1, K=256) + bn1 + silu ========
// smem: A hi [128][80B] @0 (10240), B hi @10240 (10240), B lo @20480 (10240)
__global__ __launch_bounds__(256, 2) void k1_mma(const float* __restrict__ x) {
    __shared__ char sm[30720];
    uint32_t sb = smem_u32(sm);
    int tid = threadIdx.x;
    int lane = tid & 31;
    int wid = tid >> 5;
    int b = blockIdx.y;
    int p0 = blockIdx.x * 128;

    int warp_o = (wid >> 1) * 32;
    int warp_p = (wid & 1) * 64;
    uint32_t aoff[2], boff[4];
    #pragma unroll
    for (int f = 0; f < 2; f++)
        aoff[f] = (warp_o + f*16 + (lane & 15))*80 + (lane >> 4)*16;
    #pragma unroll
    for (int gp = 0; gp < 4; gp++)
        boff[gp] = 10240 + (warp_p + (gp*2 + (lane >> 4))*8 + (lane & 7))*80
                 + ((lane >> 3) & 1)*16;

    float c[64];
    #pragma unroll
    for (int i = 0; i < 64; i++) c[i] = 0.f;

    int px = tid & 127;
    int half = tid >> 7;
    uint32_t bsh = sb + 10240 + px*80 + half*32;
    uint32_t bsl = bsh + 10240;
    const float* xb = x + (size_t)b * C1 * HW + p0 + px;

    for (int ch = 0; ch < NCHK1; ch++) {
        {
            const uint4* sh = (const uint4*)(g_w1H + ch*2048);
            #pragma unroll
            for (int r = 0; r < 2; r++) {
                int i = tid + r*256;
                uint32_t d = (i >> 2)*80 + (i & 3)*16;
                *(uint4*)(sm + d) = sh[i];
            }
        }
        {
            int c0 = ch*32 + half*16;
            float acc[16];
            #pragma unroll
            for (int jj = 0; jj < 16; jj++)
                acc[jj] = __ldg(xb + (size_t)(c0 + jj)*HW);
            split_sts16(acc, bsh, bsl);
        }
        __syncthreads();
        #pragma unroll
        for (int s = 0; s < 2; s++) {
            int kb = s * 32;
            uint32_t ah[8], bh[16], bl[16];
            LDM_X4(ah[0],ah[1],ah[2],ah[3], sb + aoff[0] + kb);
            LDM_X4(ah[4],ah[5],ah[6],ah[7], sb + aoff[1] + kb);
            #pragma unroll
            for (int gp = 0; gp < 4; gp++) {
                LDM_X4(bh[gp*4],bh[gp*4+1],bh[gp*4+2],bh[gp*4+3], sb + boff[gp] + kb);
                LDM_X4(bl[gp*4],bl[gp*4+1],bl[gp*4+2],bl[gp*4+3], sb + boff[gp] + 10240 + kb);
            }
            #pragma unroll
            for (int f = 0; f < 2; f++)
                #pragma unroll
                for (int g = 0; g < 8; g++) {
                    float* cc = &c[(f*8 + g)*4];
                    mma_f16(cc, &ah[f*4], &bh[g*2]);
                    mma_f16(cc, &ah[f*4], &bl[g*2]);
                }
        }
        __syncthreads();
    }
    #pragma unroll
    for (int f = 0; f < 2; f++) {
        #pragma unroll
        for (int ho = 0; ho < 2; ho++) {
            int o = warp_o + f*16 + (lane >> 2) + ho*8;
            float s = g_s1[o], t = g_t1[o];
            float* dst = g_y1 + ((size_t)b*CH + o)*HW + p0 + warp_p + 2*(lane & 3);
            #pragma unroll
            for (int g = 0; g < 8; g++) {
                float2 r;
                r.x = silu_f(c[(f*8+g)*4 + ho*2    ]*s + t);
                r.y = silu_f(c[(f*8+g)*4 + ho*2 + 1]*s + t);
                *(float2*)(dst + g*8) = r;
            }
        }
    }
}

// ======== k2: offset conv (M=32, K=1152, tap-major) ========
// smem: A hi [32][80B] @0 (2560), B hi @2560 (10240), B lo @12800 (10240)
__global__ __launch_bounds__(256, 2) void k2_mma(const float* __restrict__ offb) {
    __shared__ char sm[23040];
    uint32_t sb = smem_u32(sm);
    int tid = threadIdx.x;
    int lane = tid & 31;
    int wid = tid >> 5;
    int b = blockIdx.y;
    int p0 = blockIdx.x * 128;

    int warp_p = wid * 16;
    uint32_t aoff[2], boff;
    #pragma unroll
    for (int f = 0; f < 2; f++)
        aoff[f] = (f*16 + (lane & 15))*80 + (lane >> 4)*16;
    boff = 2560 + (warp_p + (lane >> 4)*8 + (lane & 7))*80 + ((lane >> 3) & 1)*16;

    float c[16];
    #pragma unroll
    for (int i = 0; i < 16; i++) c[i] = 0.f;

    int px = tid & 127;
    int half = tid >> 7;
    uint32_t bsh = sb + 2560 + px*80 + half*32;
    uint32_t bsl = bsh + 10240;
    const float* y1b = g_y1 + (size_t)b * CH * HW;
    int p = p0 + px, h = p / 80, w = p - h*80;

    for (int ch = 0; ch < NCHK; ch++) {
        if (tid < 128) {
            const uint4* sh = (const uint4*)(g_owH + ch*512);
            uint32_t d = (tid >> 2)*80 + (tid & 3)*16;
            *(uint4*)(sm + d) = sh[tid];
        }
        {
            int n = ch >> 2;
            int c0 = ((ch & 3) << 5) + half*16;
            int yy = h + n/3 - 1, xx = w + n%3 - 1;
            bool valid = (yy >= 0 && yy < Hh && xx >= 0 && xx < Ww);
            const float* src = y1b + (size_t)c0*HW + yy*Ww + xx;
            float acc[16];
            #pragma unroll
            for (int jj = 0; jj < 16; jj++)
                acc[jj] = valid ? __ldg(src + (size_t)jj*HW) : 0.f;
            split_sts16(acc, bsh, bsl);
        }
        __syncthreads();
        #pragma unroll
        for (int s = 0; s < 2; s++) {
            int kb = s * 32;
            uint32_t ah[8], bh[4], bl[4];
            LDM_X4(ah[0],ah[1],ah[2],ah[3], sb + aoff[0] + kb);
            LDM_X4(ah[4],ah[5],ah[6],ah[7], sb + aoff[1] + kb);
            LDM_X4(bh[0],bh[1],bh[2],bh[3], sb + boff + kb);
            LDM_X4(bl[0],bl[1],bl[2],bl[3], sb + boff + 10240 + kb);
            #pragma unroll
            for (int f = 0; f < 2; f++)
                #pragma unroll
                for (int g = 0; g < 2; g++) {
                    float* cc = &c[(f*2 + g)*4];
                    mma_f16(cc, &ah[f*4], &bh[g*2]);
                    mma_f16(cc, &ah[f*4], &bl[g*2]);
                }
        }
        __syncthreads();
    }
    #pragma unroll
    for (int f = 0; f < 2; f++) {
        #pragma unroll
        for (int ho = 0; ho < 2; ho++) {
            int o = f*16 + (lane >> 2) + ho*8;
            if (o < OC) {
                float bias = offb[o];
                int pp = p0 + warp_p + 2*(lane & 3);
                #pragma unroll
                for (int g = 0; g < 2; g++) {
                    float v0 = c[(f*2+g)*4 + ho*2    ] + bias;
                    float v1 = c[(f*2+g)*4 + ho*2 + 1] + bias;
                    if (o < 18) {
                        float* dst = g_off + ((size_t)b*18 + o)*HW + pp + g*8;
                        *(float2*)dst = make_float2(v0, v1);
                    } else {
                        float* dst = g_mask + ((size_t)b*NT + (o-18))*HW + pp + g*8;
                        *(float2*)dst = make_float2(1.f/(1.f + __expf(-v0)),
                                                    1.f/(1.f + __expf(-v1)));
                    }
                }
            }
        }
    }
}

// ======== k3: DCNv2 warp-specialized, 4-stage, fp16 2-term ========
// stage: A hi @0 (10240), B hi @10240 (10240), B lo @20480 (10240)
#define TI_OFF 0
#define TW_OFF 9216
#define STG_OFF 27648
#define STG_SZ  30720
#define NSTG 4
#define K3_SMEM (STG_OFF + NSTG*STG_SZ)   /* 150528 */

__global__ __launch_bounds__(512, 1) void k3_dcn_mma(const float* __restrict__ dcnb) {
    extern __shared__ char smem[];
    uint32_t sb = smem_u32(smem);
    int tid = threadIdx.x;
    int lane = tid & 31;
    int wid = tid >> 5;
    int b = blockIdx.y;
    int p0 = blockIdx.x * 128;

    short4* tbli = (short4*)(smem + TI_OFF);
    float4* tblw = (float4*)(smem + TW_OFF);
    const float* y1b = g_y1 + (size_t)b * CH * HW;

    for (int e = tid; e < NT*128; e += 512) {
        int n = e >> 7, pxe = e & 127;
        int p = p0 + pxe, h = p / 80, w = p - h * 80;
        float m  = g_mask[((size_t)b*NT + n)*HW + p];
        float dy = g_off[((size_t)b*18 + 2*n    )*HW + p];
        float dx = g_off[((size_t)b*18 + 2*n + 1)*HW + p];
        float py = (float)(h - 1 + n/3) + dy;
        float pxf= (float)(w - 1 + n%3) + dx;
        float y0f = floorf(py), x0f = floorf(pxf);
        float fy = py - y0f, fx = pxf - x0f;
        int y0 = (int)y0f, x0 = (int)x0f;
        int y1i = y0 + 1, x1i = x0 + 1;
        float vy0 = (y0  >= 0 && y0  < Hh) ? 1.f : 0.f;
        float vy1 = (y1i >= 0 && y1i < Hh) ? 1.f : 0.f;
        float vx0 = (x0  >= 0 && x0  < Ww) ? 1.f : 0.f;
        float vx1 = (x1i >= 0 && x1i < Ww) ? 1.f : 0.f;
        int cy0 = min(max(y0, 0), Hh-1) * Ww;
        int cy1 = min(max(y1i,0), Hh-1) * Ww;
        int cx0 = min(max(x0, 0), Ww-1);
        int cx1 = min(max(x1i,0), Ww-1);
        tbli[e] = make_short4((short)(cy0+cx0), (short)(cy0+cx1),
                              (short)(cy1+cx0), (short)(cy1+cx1));
        tblw[e] = make_float4(m*(1.f-fy)*(1.f-fx)*vy0*vx0,
                              m*(1.f-fy)*fx      *vy0*vx1,
                              m*fy*(1.f-fx)      *vy1*vx0,
                              m*fy*fx            *vy1*vx1);
    }
    __syncthreads();

    if (wid >= 8) {
        // ================= PRODUCER =================
        int ptid = tid - 256;
        int px = ptid & 127;
        int half = ptid >> 7;
        uint32_t brow = px*80 + half*32;
        for (int ch = 0; ch < NCHK; ch++) {
            int s = ch & (NSTG-1);
            if (ch >= NSTG) BAR_SYNC(5 + s);
            uint32_t stg = STG_OFF + s*STG_SZ;
            {
                const uint4* sh = (const uint4*)(g_dcnH + ch*2048);
                #pragma unroll
                for (int r = 0; r < 2; r++) {
                    int i = ptid + r*256;
                    uint32_t d = (i >> 2)*80 + (i & 3)*16;
                    cpasync16(sb + stg + d, sh + i);
                }
                asm volatile("cp.async.commit_group;" ::: "memory");
            }
            {
                uint32_t bbs = stg + 10240;
                int n = ch >> 2;
                int c0 = ((ch & 3) << 5) + half*16;
                float4 wv = tblw[(n << 7) + px];
                short4 iv = tbli[(n << 7) + px];
                float acc[16];
                gather16(y1b + (size_t)c0*HW, iv.x, iv.y, iv.z, iv.w, wv, acc);
                split_sts16(acc, sb + bbs + brow, sb + bbs + 10240 + brow);
            }
            asm volatile("cp.async.wait_group 0;" ::: "memory");
            asm volatile("membar.cta;" ::: "memory");
            BAR_ARRIVE(1 + s);
        }
    } else {
        // ================= CONSUMER =================
        int warp_o = (wid >> 1) * 32;
        int warp_p = (wid & 1) * 64;
        uint32_t aoffr[2], boffr[4];
        #pragma unroll
        for (int f = 0; f < 2; f++)
            aoffr[f] = (warp_o + f*16 + (lane & 15))*80 + (lane >> 4)*16;
        #pragma unroll
        for (int gp = 0; gp < 4; gp++)
            boffr[gp] = 10240 + (warp_p + (gp*2 + (lane >> 4))*8 + (lane & 7))*80
                      + ((lane >> 3) & 1)*16;

        float c[64];
        #pragma unroll
        for (int i = 0; i < 64; i++) c[i] = 0.f;

        for (int ch = 0; ch < NCHK; ch++) {
            int s = ch & (NSTG-1);
            BAR_SYNC(1 + s);
            uint32_t stg = sb + STG_OFF + s*STG_SZ;
            #pragma unroll
            for (int ks = 0; ks < 2; ks++) {
                int kb = ks * 32;
                uint32_t ah[8], bh[16], bl[16];
                LDM_X4(ah[0],ah[1],ah[2],ah[3], stg + aoffr[0] + kb);
                LDM_X4(ah[4],ah[5],ah[6],ah[7], stg + aoffr[1] + kb);
                #pragma unroll
                for (int gp = 0; gp < 4; gp++) {
                    LDM_X4(bh[gp*4],bh[gp*4+1],bh[gp*4+2],bh[gp*4+3], stg + boffr[gp] + kb);
                    LDM_X4(bl[gp*4],bl[gp*4+1],bl[gp*4+2],bl[gp*4+3], stg + boffr[gp] + 10240 + kb);
                }
                #pragma unroll
                for (int f = 0; f < 2; f++)
                    #pragma unroll
                    for (int g = 0; g < 8; g++) {
                        float* cc = &c[(f*8 + g)*4];
                        mma_f16(cc, &ah[f*4], &bh[g*2]);
                        mma_f16(cc, &ah[f*4], &bl[g*2]);
                    }
            }
            BAR_ARRIVE(5 + s);
        }

        #pragma unroll
        for (int f = 0; f < 2; f++) {
            #pragma unroll
            for (int ho = 0; ho < 2; ho++) {
                int o = warp_o + f*16 + (lane >> 2) + ho*8;
                float s = g_s2[o], t = g_t2[o], bias = dcnb[o];
                float* dst = g_z + ((size_t)b*CH + o)*HW + p0 + warp_p + 2*(lane & 3);
                #pragma unroll
                for (int g = 0; g < 8; g++) {
                    float2 r;
                    r.x = silu_f((c[(f*8+g)*4 + ho*2    ] + bias)*s + t);
                    r.y = silu_f((c[(f*8+g)*4 + ho*2 + 1] + bias)*s + t);
                    *(float2*)(dst + g*8) = r;
                }
            }
        }
    }
}

// ======== k4: cv2 (1x1, K=128) + bn3 + silu + residual ========
__global__ __launch_bounds__(256, 2) void k4_mma(const float* __restrict__ x,
                                                 float* __restrict__ out) {
    __shared__ char sm[30720];
    uint32_t sb = smem_u32(sm);
    int tid = threadIdx.x;
    int lane = tid & 31;
    int wid = tid >> 5;
    int b = blockIdx.y;
    int p0 = blockIdx.x * 128;
    int z = blockIdx.z;

    int warp_o = (wid >> 1) * 32;
    int warp_p = (wid & 1) * 64;
    uint32_t aoff[2], boff[4];
    #pragma unroll
    for (int f = 0; f < 2; f++)
        aoff[f] = (warp_o + f*16 + (lane & 15))*80 + (lane >> 4)*16;
    #pragma unroll
    for (int gp = 0; gp < 4; gp++)
        boff[gp] = 10240 + (warp_p + (gp*2 + (lane >> 4))*8 + (lane & 7))*80
                 + ((lane >> 3) & 1)*16;

    float c[64];
    #pragma unroll
    for (int i = 0; i < 64; i++) c[i] = 0.f;

    int px = tid & 127;
    int half = tid >> 7;
    uint32_t bsh = sb + 10240 + px*80 + half*32;
    uint32_t bsl = bsh + 10240;
    const float* zb = g_z + (size_t)b * CH * HW + p0 + px;

    for (int ch = 0; ch < NCHK4; ch++) {
        {
            const uint4* sh = (const uint4*)(g_w2H + (z*NCHK4 + ch)*2048);
            #pragma unroll
            for (int r = 0; r < 2; r++) {
                int i = tid + r*256;
                uint32_t d = (i >> 2)*80 + (i & 3)*16;
                *(uint4*)(sm + d) = sh[i];
            }
        }
        {
            int c0 = ch*32 + half*16;
            float acc[16];
            #pragma unroll
            for (int jj = 0; jj < 16; jj++)
                acc[jj] = __ldg(zb + (size_t)(c0 + jj)*HW);
            split_sts16(acc, bsh, bsl);
        }
        __syncthreads();
        #pragma unroll
        for (int s = 0; s < 2; s++) {
            int kb = s * 32;
            uint32_t ah[8], bh[16], bl[16];
            LDM_X4(ah[0],ah[1],ah[2],ah[3], sb + aoff[0] + kb);
            LDM_X4(ah[4],ah[5],ah[6],ah[7], sb + aoff[1] + kb);
            #pragma unroll
            for (int gp = 0; gp < 4; gp++) {
                LDM_X4(bh[gp*4],bh[gp*4+1],bh[gp*4+2],bh[gp*4+3], sb + boff[gp] + kb);
                LDM_X4(bl[gp*4],bl[gp*4+1],bl[gp*4+2],bl[gp*4+3], sb + boff[gp] + 10240 + kb);
            }
            #pragma unroll
            for (int f = 0; f < 2; f++)
                #pragma unroll
                for (int g = 0; g < 8; g++) {
                    float* cc = &c[(f*8 + g)*4];
                    mma_f16(cc, &ah[f*4], &bh[g*2]);
                    mma_f16(cc, &ah[f*4], &bl[g*2]);
                }
        }
        __syncthreads();
    }
    #pragma unroll
    for (int f = 0; f < 2; f++) {
        #pragma unroll
        for (int ho = 0; ho < 2; ho++) {
            int o = z*128 + warp_o + f*16 + (lane >> 2) + ho*8;
            float s = g_s3[o], t = g_t3[o];
            size_t base = ((size_t)b*C2 + o)*HW + p0 + warp_p + 2*(lane & 3);
            #pragma unroll
            for (int g = 0; g < 8; g++) {
                float2 xr = *(const float2*)(x + base + g*8);
                float2 r;
                r.x = silu_f(c[(f*8+g)*4 + ho*2    ]*s + t) + xr.x;
                r.y = silu_f(c[(f*8+g)*4 + ho*2 + 1]*s + t) + xr.y;
                *(float2*)(out + base + g*8) = r;
            }
        }
    }
}

extern "C" void kernel_launch(void* const* d_in, const int* in_sizes, int n_in,
                              void* d_out, int out_size) {
    const float* x     = (const float*)d_in[0];
    const float* cv1w  = (const float*)d_in[1];
    const float* bn1g  = (const float*)d_in[2];
    const float* bn1b  = (const float*)d_in[3];
    const float* bn1m  = (const float*)d_in[4];
    const float* bn1v  = (const float*)d_in[5];
    const float* offw  = (const float*)d_in[6];
    const float* offb  = (const float*)d_in[7];
    const float* dcnw  = (const float*)d_in[8];
    const float* dcnb  = (const float*)d_in[9];
    const float* bn2g  = (const float*)d_in[10];
    const float* bn2b  = (const float*)d_in[11];
    const float* bn2m  = (const float*)d_in[12];
    const float* bn2v  = (const float*)d_in[13];
    const float* cv2w  = (const float*)d_in[14];
    const float* bn3g  = (const float*)d_in[15];
    const float* bn3b  = (const float*)d_in[16];
    const float* bn3m  = (const float*)d_in[17];
    const float* bn3v  = (const float*)d_in[18];
    float* out = (float*)d_out;

    cudaFuncSetAttribute(k3_dcn_mma, cudaFuncAttributeMaxDynamicSharedMemorySize, K3_SMEM);

    prep_kernel<<<2048, 256>>>(cv1w, bn1g, bn1b, bn1m, bn1v, offw, dcnw,
                               bn2g, bn2b, bn2m, bn2v, cv2w, bn3g, bn3b, bn3m, bn3v);
    k1_mma<<<dim3(HW/128, Bn), 256>>>(x);
    k2_mma<<<dim3(HW/128, Bn), 256>>>(offb);
    k3_dcn_mma<<<dim3(HW/128, Bn), 512, K3_SMEM>>>(dcnb);
    k4_mma<<<dim3(HW/128, Bn, 2), 256>>>(x, out);
}

// round 15
// speedup vs baseline: 1.2291x; 1.2291x over previous
#include <cuda_runtime.h>
#include <cuda_bf16.h>
#include <math.h>
#include <stdint.h>

#define Bn 8
#define C1 256
#define CH 128
#define C2 256
#define Hh 80
#define Ww 80
#define HW 6400
#define NT 9
#define KT 1152
#define OC 27
#define NCHK 36   /* k3/k2 K chunks of 32, k' = n*128 + c */
#define NCHK1 8   /* k1: K=256 */
#define NCHK4 4   /* k4: K=128 */

// -------- scratch --------
__device__ float g_y1[Bn*CH*HW];     // post cv1+bn1+silu, [b][c][hw]
__device__ float g_z[Bn*CH*HW];      // post dcn+bn2+silu, [b][c][hw]
__device__ float g_off[Bn*18*HW];
__device__ float g_mask[Bn*NT*HW];
__device__ uint32_t g_dcnHi[NCHK*2048];
__device__ uint32_t g_dcnLo[NCHK*2048];
__device__ uint32_t g_w1Hi[NCHK1*2048];
__device__ uint32_t g_w1Lo[NCHK1*2048];
__device__ uint32_t g_w2Hi[2*NCHK4*2048];
__device__ uint32_t g_w2Lo[2*NCHK4*2048];
__device__ uint32_t g_owHi[NCHK*512];
__device__ uint32_t g_owLo[NCHK*512];
__device__ float g_s1[CH], g_t1[CH], g_s2[CH], g_t2[CH], g_s3[C2], g_t3[C2];

__device__ __forceinline__ float silu_f(float v) { return v / (1.f + __expf(-v)); }

__device__ __forceinline__ uint32_t pack2bf(float a, float b) {
    __nv_bfloat162 t = __floats2bfloat162_rn(a, b);
    return *(uint32_t*)&t;
}
__device__ __forceinline__ uint32_t smem_u32(const void* p) {
    uint32_t a; asm("{ .reg .u64 t; cvta.to.shared.u64 t, %1; cvt.u32.u64 %0, t; }" : "=r"(a) : "l"(p));
    return a;
}
#define LDM_X4(r0,r1,r2,r3,addr) \
    asm volatile("ldmatrix.sync.aligned.m8n8.x4.shared.b16 {%0,%1,%2,%3}, [%4];" \
        : "=r"(r0),"=r"(r1),"=r"(r2),"=r"(r3) : "r"(addr))

__device__ __forceinline__ void mma_bf16(float* c, const uint32_t* a, const uint32_t* b) {
    asm volatile(
        "mma.sync.aligned.m16n8k16.row.col.f32.bf16.bf16.f32 "
        "{%0,%1,%2,%3}, {%4,%5,%6,%7}, {%8,%9}, {%0,%1,%2,%3};"
        : "+f"(c[0]), "+f"(c[1]), "+f"(c[2]), "+f"(c[3])
        : "r"(a[0]), "r"(a[1]), "r"(a[2]), "r"(a[3]), "r"(b[0]), "r"(b[1]));
}
__device__ __forceinline__ void split_pack(float w0, float w1, uint32_t* hi, uint32_t* lo) {
    float h0 = __bfloat162float(__float2bfloat16(w0));
    float h1 = __bfloat162float(__float2bfloat16(w1));
    *hi = pack2bf(h0, h1);
    *lo = pack2bf(w0 - h0, w1 - h1);
}
__device__ __forceinline__ void cpasync16(uint32_t dst, const void* src) {
    asm volatile("cp.async.cg.shared.global [%0], [%1], 16;" :: "r"(dst), "l"(src) : "memory");
}
__device__ __forceinline__ void split_sts16(const float* acc, uint32_t dh, uint32_t dl) {
    #pragma unroll
    for (int q = 0; q < 2; q++) {
        uint32_t ph[4], pl[4];
        #pragma unroll
        for (int jj = 0; jj < 4; jj++)
            split_pack(acc[q*8 + jj*2], acc[q*8 + jj*2 + 1], &ph[jj], &pl[jj]);
        asm volatile("st.shared.v4.b32 [%0], {%1,%2,%3,%4};" ::
            "r"(dh + q*16), "r"(ph[0]), "r"(ph[1]), "r"(ph[2]), "r"(ph[3]));
        asm volatile("st.shared.v4.b32 [%0], {%1,%2,%3,%4};" ::
            "r"(dl + q*16), "r"(pl[0]), "r"(pl[1]), "r"(pl[2]), "r"(pl[3]));
    }
}
#define BAR_SYNC(id)   asm volatile("bar.sync %0, 512;"   :: "r"(id) : "memory")
#define BAR_ARRIVE(id) asm volatile("bar.arrive %0, 512;" :: "r"(id) : "memory")

// high-MLP bilinear gather for 16 channels
__device__ __forceinline__ void gather16(const float* pb, int i0, int i1, int i2, int i3,
                                         float4 wv, float* acc) {
    float l0[16], l1[16];
    #pragma unroll
    for (int jj = 0; jj < 16; jj++) l0[jj] = __ldg(pb + (size_t)jj*HW + i0);
    #pragma unroll
    for (int jj = 0; jj < 16; jj++) l1[jj] = __ldg(pb + (size_t)jj*HW + i1);
    #pragma unroll
    for (int jj = 0; jj < 16; jj++) acc[jj] = wv.x*l0[jj] + wv.y*l1[jj];
    #pragma unroll
    for (int jj = 0; jj < 16; jj++) l0[jj] = __ldg(pb + (size_t)jj*HW + i2);
    #pragma unroll
    for (int jj = 0; jj < 16; jj++) l1[jj] = __ldg(pb + (size_t)jj*HW + i3);
    #pragma unroll
    for (int jj = 0; jj < 16; jj++) acc[jj] += wv.z*l0[jj] + wv.w*l1[jj];
}

// -------- prep --------
__global__ void prep_kernel(const float* __restrict__ cv1w,
                            const float* __restrict__ bn1g, const float* __restrict__ bn1b,
                            const float* __restrict__ bn1m, const float* __restrict__ bn1v,
                            const float* __restrict__ offw, const float* __restrict__ dcnw,
                            const float* __restrict__ bn2g, const float* __restrict__ bn2b,
                            const float* __restrict__ bn2m, const float* __restrict__ bn2v,
                            const float* __restrict__ cv2w,
                            const float* __restrict__ bn3g, const float* __restrict__ bn3b,
                            const float* __restrict__ bn3m, const float* __restrict__ bn3v) {
    int idx0 = blockIdx.x * blockDim.x + threadIdx.x;
    int stride = gridDim.x * blockDim.x;
    for (int i = idx0; i < NCHK*2048; i += stride) {
        int ch = i >> 11, r = i & 2047;
        int o = r >> 4, kp = r & 15;
        int kk = ch*32 + kp*2;
        int n = kk >> 7, c = kk & 127;
        split_pack(dcnw[o*KT + c*9 + n], dcnw[o*KT + (c+1)*9 + n], &g_dcnHi[i], &g_dcnLo[i]);
    }
    for (int i = idx0; i < NCHK1*2048; i += stride) {
        int ch = i >> 11, r = i & 2047;
        int o = r >> 4, kp = r & 15;
        int c = ch*32 + kp*2;
        split_pack(cv1w[o*C1 + c], cv1w[o*C1 + c + 1], &g_w1Hi[i], &g_w1Lo[i]);
    }
    for (int i = idx0; i < 2*NCHK4*2048; i += stride) {
        int z = i >> 13, r1 = i & 8191;
        int ch = r1 >> 11, r = r1 & 2047;
        int o = r >> 4, kp = r & 15;
        int c = ch*32 + kp*2;
        split_pack(cv2w[(z*128+o)*CH + c], cv2w[(z*128+o)*CH + c + 1], &g_w2Hi[i], &g_w2Lo[i]);
    }
    for (int i = idx0; i < NCHK*512; i += stride) {
        int ch = i >> 9, r = i & 511;
        int o = r >> 4, kp = r & 15;
        int kk = ch*32 + kp*2;
        int n = kk >> 7, c = kk & 127;
        float w0 = (o < OC) ? offw[o*KT + c*9 + n] : 0.f;
        float w1 = (o < OC) ? offw[o*KT + (c+1)*9 + n] : 0.f;
        split_pack(w0, w1, &g_owHi[i], &g_owLo[i]);
    }
    for (int i = idx0; i < CH; i += stride) {
        float s = bn1g[i] * rsqrtf(bn1v[i] + 1e-5f);
        g_s1[i] = s; g_t1[i] = bn1b[i] - bn1m[i]*s;
        float s2 = bn2g[i] * rsqrtf(bn2v[i] + 1e-5f);
        g_s2[i] = s2; g_t2[i] = bn2b[i] - bn2m[i]*s2;
    }
    for (int i = idx0; i < C2; i += stride) {
        float s = bn3g[i] * rsqrtf(bn3v[i] + 1e-5f);
        g_s3[i] = s; g_t3[i] = bn3b[i] - bn3m[i]*s;
    }
}

// ======== k1: cv1 (1x1, K=256) + bn1 + silu, 256-px tiles, 512 thr ========
// smem: AH @0 (10240), AL @10240, BH @20480 (20480), BL @40960 (20480) = 61440
__global__ __launch_bounds__(512, 1) void k1_mma(const float* __restrict__ x) {
    __shared__ char sm[61440];
    uint32_t sb = smem_u32(sm);
    int tid = threadIdx.x;
    int lane = tid & 31;
    int wid = tid >> 5;
    int b = blockIdx.y;
    int p0 = blockIdx.x * 256;

    int warp_o = (wid >> 2) * 32;
    int warp_p = (wid & 3) * 64;
    uint32_t aoff[2], boff[4];
    #pragma unroll
    for (int f = 0; f < 2; f++)
        aoff[f] = (warp_o + f*16 + (lane & 15))*80 + (lane >> 4)*16;
    #pragma unroll
    for (int gp = 0; gp < 4; gp++)
        boff[gp] = 20480 + (warp_p + (gp*2 + (lane >> 4))*8 + (lane & 7))*80
                 + ((lane >> 3) & 1)*16;

    float c[64];
    #pragma unroll
    for (int i = 0; i < 64; i++) c[i] = 0.f;

    int px = tid & 255;
    int half = tid >> 8;
    uint32_t bsh = sb + 20480 + px*80 + half*32;
    uint32_t bsl = bsh + 20480;
    const float* xb = x + (size_t)b * C1 * HW + p0 + px;

    for (int ch = 0; ch < NCHK1; ch++) {
        {
            const uint4* sh = (const uint4*)(g_w1Hi + ch*2048);
            const uint4* sl = (const uint4*)(g_w1Lo + ch*2048);
            uint32_t d = (tid >> 2)*80 + (tid & 3)*16;
            *(uint4*)(sm + d) = sh[tid];
            *(uint4*)(sm + 10240 + d) = sl[tid];
        }
        {
            int c0 = ch*32 + half*16;
            float acc[16];
            #pragma unroll
            for (int jj = 0; jj < 16; jj++)
                acc[jj] = __ldg(xb + (size_t)(c0 + jj)*HW);
            split_sts16(acc, bsh, bsl);
        }
        __syncthreads();
        #pragma unroll
        for (int s = 0; s < 2; s++) {
            int kb = s * 32;
            uint32_t ah[8], al[8], bh[16], bl[16];
            LDM_X4(ah[0],ah[1],ah[2],ah[3], sb + aoff[0] + kb);
            LDM_X4(ah[4],ah[5],ah[6],ah[7], sb + aoff[1] + kb);
            LDM_X4(al[0],al[1],al[2],al[3], sb + aoff[0] + 10240 + kb);
            LDM_X4(al[4],al[5],al[6],al[7], sb + aoff[1] + 10240 + kb);
            #pragma unroll
            for (int gp = 0; gp < 4; gp++) {
                LDM_X4(bh[gp*4],bh[gp*4+1],bh[gp*4+2],bh[gp*4+3], sb + boff[gp] + kb);
                LDM_X4(bl[gp*4],bl[gp*4+1],bl[gp*4+2],bl[gp*4+3], sb + boff[gp] + 20480 + kb);
            }
            #pragma unroll
            for (int f = 0; f < 2; f++)
                #pragma unroll
                for (int g = 0; g < 8; g++) {
                    float* cc = &c[(f*8 + g)*4];
                    mma_bf16(cc, &ah[f*4], &bh[g*2]);
                    mma_bf16(cc, &al[f*4], &bh[g*2]);
                    mma_bf16(cc, &ah[f*4], &bl[g*2]);
                }
        }
        __syncthreads();
    }
    #pragma unroll
    for (int f = 0; f < 2; f++) {
        #pragma unroll
        for (int ho = 0; ho < 2; ho++) {
            int o = warp_o + f*16 + (lane >> 2) + ho*8;
            float s = g_s1[o], t = g_t1[o];
            float* dst = g_y1 + ((size_t)b*CH + o)*HW + p0 + warp_p + 2*(lane & 3);
            #pragma unroll
            for (int g = 0; g < 8; g++) {
                float2 r;
                r.x = silu_f(c[(f*8+g)*4 + ho*2    ]*s + t);
                r.y = silu_f(c[(f*8+g)*4 + ho*2 + 1]*s + t);
                *(float2*)(dst + g*8) = r;
            }
        }
    }
}

// ======== k2: offset conv (M=32, K=1152, tap-major) — R13 version ========
__global__ __launch_bounds__(256, 2) void k2_mma(const float* __restrict__ offb) {
    __shared__ char sm[25600];
    uint32_t sb = smem_u32(sm);
    int tid = threadIdx.x;
    int lane = tid & 31;
    int wid = tid >> 5;
    int b = blockIdx.y;
    int p0 = blockIdx.x * 128;

    int warp_p = wid * 16;
    uint32_t aoff[2], boff;
    #pragma unroll
    for (int f = 0; f < 2; f++)
        aoff[f] = (f*16 + (lane & 15))*80 + (lane >> 4)*16;
    boff = 5120 + (warp_p + (lane >> 4)*8 + (lane & 7))*80 + ((lane >> 3) & 1)*16;

    float c[16];
    #pragma unroll
    for (int i = 0; i < 16; i++) c[i] = 0.f;

    int px = tid & 127;
    int half = tid >> 7;
    uint32_t bsh = sb + 5120 + px*80 + half*32;
    uint32_t bsl = sb + 15360 + px*80 + half*32;
    const float* y1b = g_y1 + (size_t)b * CH * HW;
    int p = p0 + px, h = p / 80, w = p - h*80;

    for (int ch = 0; ch < NCHK; ch++) {
        if (tid < 128) {
            const uint4* sh = (const uint4*)(g_owHi + ch*512);
            const uint4* sl = (const uint4*)(g_owLo + ch*512);
            uint32_t d = (tid >> 2)*80 + (tid & 3)*16;
            *(uint4*)(sm + d) = sh[tid];
            *(uint4*)(sm + 2560 + d) = sl[tid];
        }
        {
            int n = ch >> 2;
            int c0 = ((ch & 3) << 5) + half*16;
            int yy = h + n/3 - 1, xx = w + n%3 - 1;
            bool valid = (yy >= 0 && yy < Hh && xx >= 0 && xx < Ww);
            const float* src = y1b + (size_t)c0*HW + yy*Ww + xx;
            float acc[16];
            #pragma unroll
            for (int jj = 0; jj < 16; jj++)
                acc[jj] = valid ? __ldg(src + (size_t)jj*HW) : 0.f;
            split_sts16(acc, bsh, bsl);
        }
        __syncthreads();
        #pragma unroll
        for (int s = 0; s < 2; s++) {
            int kb = s * 32;
            uint32_t ah[8], al[8], bh[4], bl[4];
            LDM_X4(ah[0],ah[1],ah[2],ah[3], sb + aoff[0] + kb);
            LDM_X4(ah[4],ah[5],ah[6],ah[7], sb + aoff[1] + kb);
            LDM_X4(al[0],al[1],al[2],al[3], sb + aoff[0] + 2560 + kb);
            LDM_X4(al[4],al[5],al[6],al[7], sb + aoff[1] + 2560 + kb);
            LDM_X4(bh[0],bh[1],bh[2],bh[3], sb + boff + kb);
            LDM_X4(bl[0],bl[1],bl[2],bl[3], sb + boff + 10240 + kb);
            #pragma unroll
            for (int f = 0; f < 2; f++)
                #pragma unroll
                for (int g = 0; g < 2; g++) {
                    float* cc = &c[(f*2 + g)*4];
                    mma_bf16(cc, &ah[f*4], &bh[g*2]);
                    mma_bf16(cc, &al[f*4], &bh[g*2]);
                    mma_bf16(cc, &ah[f*4], &bl[g*2]);
                }
        }
        __syncthreads();
    }
    #pragma unroll
    for (int f = 0; f < 2; f++) {
        #pragma unroll
        for (int ho = 0; ho < 2; ho++) {
            int o = f*16 + (lane >> 2) + ho*8;
            if (o < OC) {
                float bias = offb[o];
                int pp = p0 + warp_p + 2*(lane & 3);
                #pragma unroll
                for (int g = 0; g < 2; g++) {
                    float v0 = c[(f*2+g)*4 + ho*2    ] + bias;
                    float v1 = c[(f*2+g)*4 + ho*2 + 1] + bias;
                    if (o < 18) {
                        float* dst = g_off + ((size_t)b*18 + o)*HW + pp + g*8;
                        *(float2*)dst = make_float2(v0, v1);
                    } else {
                        float* dst = g_mask + ((size_t)b*NT + (o-18))*HW + pp + g*8;
                        *(float2*)dst = make_float2(1.f/(1.f + __expf(-v0)),
                                                    1.f/(1.f + __expf(-v1)));
                    }
                }
            }
        }
    }
}

// ======== k3: DCNv2 warp-specialized, 4-stage, bf16 3-term — R13 version ========
#define TI_OFF 0
#define TW_OFF 9216
#define STG_OFF 27648
#define STG_SZ  40960
#define NSTG 4
#define K3_SMEM (STG_OFF + NSTG*STG_SZ)   /* 191488 */

__global__ __launch_bounds__(512, 1) void k3_dcn_mma(const float* __restrict__ dcnb) {
    extern __shared__ char smem[];
    uint32_t sb = smem_u32(smem);
    int tid = threadIdx.x;
    int lane = tid & 31;
    int wid = tid >> 5;
    int b = blockIdx.y;
    int p0 = blockIdx.x * 128;

    short4* tbli = (short4*)(smem + TI_OFF);
    float4* tblw = (float4*)(smem + TW_OFF);
    const float* y1b = g_y1 + (size_t)b * CH * HW;

    for (int e = tid; e < NT*128; e += 512) {
        int n = e >> 7, pxe = e & 127;
        int p = p0 + pxe, h = p / 80, w = p - h * 80;
        float m  = g_mask[((size_t)b*NT + n)*HW + p];
        float dy = g_off[((size_t)b*18 + 2*n    )*HW + p];
        float dx = g_off[((size_t)b*18 + 2*n + 1)*HW + p];
        float py = (float)(h - 1 + n/3) + dy;
        float pxf= (float)(w - 1 + n%3) + dx;
        float y0f = floorf(py), x0f = floorf(pxf);
        float fy = py - y0f, fx = pxf - x0f;
        int y0 = (int)y0f, x0 = (int)x0f;
        int y1i = y0 + 1, x1i = x0 + 1;
        float vy0 = (y0  >= 0 && y0  < Hh) ? 1.f : 0.f;
        float vy1 = (y1i >= 0 && y1i < Hh) ? 1.f : 0.f;
        float vx0 = (x0  >= 0 && x0  < Ww) ? 1.f : 0.f;
        float vx1 = (x1i >= 0 && x1i < Ww) ? 1.f : 0.f;
        int cy0 = min(max(y0, 0), Hh-1) * Ww;
        int cy1 = min(max(y1i,0), Hh-1) * Ww;
        int cx0 = min(max(x0, 0), Ww-1);
        int cx1 = min(max(x1i,0), Ww-1);
        tbli[e] = make_short4((short)(cy0+cx0), (short)(cy0+cx1),
                              (short)(cy1+cx0), (short)(cy1+cx1));
        tblw[e] = make_float4(m*(1.f-fy)*(1.f-fx)*vy0*vx0,
                              m*(1.f-fy)*fx      *vy0*vx1,
                              m*fy*(1.f-fx)      *vy1*vx0,
                              m*fy*fx            *vy1*vx1);
    }
    __syncthreads();

    if (wid >= 8) {
        // PRODUCER
        int ptid = tid - 256;
        int px = ptid & 127;
        int half = ptid >> 7;
        uint32_t brow = px*80 + half*32;
        for (int ch = 0; ch < NCHK; ch++) {
            int s = ch & (NSTG-1);
            if (ch >= NSTG) BAR_SYNC(5 + s);
            uint32_t stg = STG_OFF + s*STG_SZ;
            {
                const uint4* sh = (const uint4*)(g_dcnHi + ch*2048);
                const uint4* sl = (const uint4*)(g_dcnLo + ch*2048);
                #pragma unroll
                for (int r = 0; r < 2; r++) {
                    int i = ptid + r*256;
                    uint32_t d = (i >> 2)*80 + (i & 3)*16;
                    cpasync16(sb + stg + d, sh + i);
                    cpasync16(sb + stg + 10240 + d, sl + i);
                }
                asm volatile("cp.async.commit_group;" ::: "memory");
            }
            {
                uint32_t bbs = stg + 20480;
                int n = ch >> 2;
                int c0 = ((ch & 3) << 5) + half*16;
                float4 wv = tblw[(n << 7) + px];
                short4 iv = tbli[(n << 7) + px];
                float acc[16];
                gather16(y1b + (size_t)c0*HW, iv.x, iv.y, iv.z, iv.w, wv, acc);
                split_sts16(acc, sb + bbs + brow, sb + bbs + 10240 + brow);
            }
            asm volatile("cp.async.wait_group 0;" ::: "memory");
            asm volatile("membar.cta;" ::: "memory");
            BAR_ARRIVE(1 + s);
        }
    } else {
        // CONSUMER
        int warp_o = (wid >> 1) * 32;
        int warp_p = (wid & 1) * 64;
        uint32_t aoffr[2], boffr[4];
        #pragma unroll
        for (int f = 0; f < 2; f++)
            aoffr[f] = (warp_o + f*16 + (lane & 15))*80 + (lane >> 4)*16;
        #pragma unroll
        for (int gp = 0; gp < 4; gp++)
            boffr[gp] = 20480 + (warp_p + (gp*2 + (lane >> 4))*8 + (lane & 7))*80
                      + ((lane >> 3) & 1)*16;

        float c[64];
        #pragma unroll
        for (int i = 0; i < 64; i++) c[i] = 0.f;

        for (int ch = 0; ch < NCHK; ch++) {
            int s = ch & (NSTG-1);
            BAR_SYNC(1 + s);
            uint32_t stg = sb + STG_OFF + s*STG_SZ;
            #pragma unroll
            for (int ks = 0; ks < 2; ks++) {
                int kb = ks * 32;
                uint32_t ah[8], al[8], bh[16], bl[16];
                LDM_X4(ah[0],ah[1],ah[2],ah[3], stg + aoffr[0] + kb);
                LDM_X4(ah[4],ah[5],ah[6],ah[7], stg + aoffr[1] + kb);
                LDM_X4(al[0],al[1],al[2],al[3], stg + aoffr[0] + 10240 + kb);
                LDM_X4(al[4],al[5],al[6],al[7], stg + aoffr[1] + 10240 + kb);
                #pragma unroll
                for (int gp = 0; gp < 4; gp++) {
                    LDM_X4(bh[gp*4],bh[gp*4+1],bh[gp*4+2],bh[gp*4+3], stg + boffr[gp] + kb);
                    LDM_X4(bl[gp*4],bl[gp*4+1],bl[gp*4+2],bl[gp*4+3], stg + boffr[gp] + 10240 + kb);
                }
                #pragma unroll
                for (int f = 0; f < 2; f++)
                    #pragma unroll
                    for (int g = 0; g < 8; g++) {
                        float* cc = &c[(f*8 + g)*4];
                        mma_bf16(cc, &ah[f*4], &bh[g*2]);
                        mma_bf16(cc, &al[f*4], &bh[g*2]);
                        mma_bf16(cc, &ah[f*4], &bl[g*2]);
                    }
            }
            BAR_ARRIVE(5 + s);
        }

        #pragma unroll
        for (int f = 0; f < 2; f++) {
            #pragma unroll
            for (int ho = 0; ho < 2; ho++) {
                int o = warp_o + f*16 + (lane >> 2) + ho*8;
                float s = g_s2[o], t = g_t2[o], bias = dcnb[o];
                float* dst = g_z + ((size_t)b*CH + o)*HW + p0 + warp_p + 2*(lane & 3);
                #pragma unroll
                for (int g = 0; g < 8; g++) {
                    float2 r;
                    r.x = silu_f((c[(f*8+g)*4 + ho*2    ] + bias)*s + t);
                    r.y = silu_f((c[(f*8+g)*4 + ho*2 + 1] + bias)*s + t);
                    *(float2*)(dst + g*8) = r;
                }
            }
        }
    }
}

// ======== k4: cv2 (1x1, K=128) + bn3 + silu + residual, 256-px tiles ========
// smem: AH @0 (10240), AL @10240, BH @20480 (20480), BL @40960 (20480) = 61440
__global__ __launch_bounds__(512, 1) void k4_mma(const float* __restrict__ x,
                                                 float* __restrict__ out) {
    __shared__ char sm[61440];
    uint32_t sb = smem_u32(sm);
    int tid = threadIdx.x;
    int lane = tid & 31;
    int wid = tid >> 5;
    int b = blockIdx.y;
    int p0 = blockIdx.x * 256;
    int z = blockIdx.z;

    int warp_o = (wid >> 2) * 32;
    int warp_p = (wid & 3) * 64;
    uint32_t aoff[2], boff[4];
    #pragma unroll
    for (int f = 0; f < 2; f++)
        aoff[f] = (warp_o + f*16 + (lane & 15))*80 + (lane >> 4)*16;
    #pragma unroll
    for (int gp = 0; gp < 4; gp++)
        boff[gp] = 20480 + (warp_p + (gp*2 + (lane >> 4))*8 + (lane & 7))*80
                 + ((lane >> 3) & 1)*16;

    float c[64];
    #pragma unroll
    for (int i = 0; i < 64; i++) c[i] = 0.f;

    int px = tid & 255;
    int half = tid >> 8;
    uint32_t bsh = sb + 20480 + px*80 + half*32;
    uint32_t bsl = bsh + 20480;
    const float* zb = g_z + (size_t)b * CH * HW + p0 + px;

    for (int ch = 0; ch < NCHK4; ch++) {
        {
            const uint4* sh = (const uint4*)(g_w2Hi + (z*NCHK4 + ch)*2048);
            const uint4* sl = (const uint4*)(g_w2Lo + (z*NCHK4 + ch)*2048);
            uint32_t d = (tid >> 2)*80 + (tid & 3)*16;
            *(uint4*)(sm + d) = sh[tid];
            *(uint4*)(sm + 10240 + d) = sl[tid];
        }
        {
            int c0 = ch*32 + half*16;
            float acc[16];
            #pragma unroll
            for (int jj = 0; jj < 16; jj++)
                acc[jj] = __ldg(zb + (size_t)(c0 + jj)*HW);
            split_sts16(acc, bsh, bsl);
        }
        __syncthreads();
        #pragma unroll
        for (int s = 0; s < 2; s++) {
            int kb = s * 32;
            uint32_t ah[8], al[8], bh[16], bl[16];
            LDM_X4(ah[0],ah[1],ah[2],ah[3], sb + aoff[0] + kb);
            LDM_X4(ah[4],ah[5],ah[6],ah[7], sb + aoff[1] + kb);
            LDM_X4(al[0],al[1],al[2],al[3], sb + aoff[0] + 10240 + kb);
            LDM_X4(al[4],al[5],al[6],al[7], sb + aoff[1] + 10240 + kb);
            #pragma unroll
            for (int gp = 0; gp < 4; gp++) {
                LDM_X4(bh[gp*4],bh[gp*4+1],bh[gp*4+2],bh[gp*4+3], sb + boff[gp] + kb);
                LDM_X4(bl[gp*4],bl[gp*4+1],bl[gp*4+2],bl[gp*4+3], sb + boff[gp] + 20480 + kb);
            }
            #pragma unroll
            for (int f = 0; f < 2; f++)
                #pragma unroll
                for (int g = 0; g < 8; g++) {
                    float* cc = &c[(f*8 + g)*4];
                    mma_bf16(cc, &ah[f*4], &bh[g*2]);
                    mma_bf16(cc, &al[f*4], &bh[g*2]);
                    mma_bf16(cc, &ah[f*4], &bl[g*2]);
                }
        }
        __syncthreads();
    }
    #pragma unroll
    for (int f = 0; f < 2; f++) {
        #pragma unroll
        for (int ho = 0; ho < 2; ho++) {
            int o = z*128 + warp_o + f*16 + (lane >> 2) + ho*8;
            float s = g_s3[o], t = g_t3[o];
            size_t base = ((size_t)b*C2 + o)*HW + p0 + warp_p + 2*(lane & 3);
            #pragma unroll
            for (int g = 0; g < 8; g++) {
                float2 xr = *(const float2*)(x + base + g*8);
                float2 r;
                r.x = silu_f(c[(f*8+g)*4 + ho*2    ]*s + t) + xr.x;
                r.y = silu_f(c[(f*8+g)*4 + ho*2 + 1]*s + t) + xr.y;
                *(float2*)(out + base + g*8) = r;
            }
        }
    }
}

extern "C" void kernel_launch(void* const* d_in, const int* in_sizes, int n_in,
                              void* d_out, int out_size) {
    const float* x     = (const float*)d_in[0];
    const float* cv1w  = (const float*)d_in[1];
    const float* bn1g  = (const float*)d_in[2];
    const float* bn1b  = (const float*)d_in[3];
    const float* bn1m  = (const float*)d_in[4];
    const float* bn1v  = (const float*)d_in[5];
    const float* offw  = (const float*)d_in[6];
    const float* offb  = (const float*)d_in[7];
    const float* dcnw  = (const float*)d_in[8];
    const float* dcnb  = (const float*)d_in[9];
    const float* bn2g  = (const float*)d_in[10];
    const float* bn2b  = (const float*)d_in[11];
    const float* bn2m  = (const float*)d_in[12];
    const float* bn2v  = (const float*)d_in[13];
    const float* cv2w  = (const float*)d_in[14];
    const float* bn3g  = (const float*)d_in[15];
    const float* bn3b  = (const float*)d_in[16];
    const float* bn3m  = (const float*)d_in[17];
    const float* bn3v  = (const float*)d_in[18];
    float* out = (float*)d_out;

    cudaFuncSetAttribute(k3_dcn_mma, cudaFuncAttributeMaxDynamicSharedMemorySize, K3_SMEM);

    prep_kernel<<<2048, 256>>>(cv1w, bn1g, bn1b, bn1m, bn1v, offw, dcnw,
                               bn2g, bn2b, bn2m, bn2v, cv2w, bn3g, bn3b, bn3m, bn3v);
    k1_mma<<<dim3(HW/256, Bn), 512>>>(x);
    k2_mma<<<dim3(HW/128, Bn), 256>>>(offb);
    k3_dcn_mma<<<dim3(HW/128, Bn), 512, K3_SMEM>>>(dcnb);
    k4_mma<<<dim3(HW/256, Bn, 2), 512>>>(x, out);
}

// round 17
// speedup vs baseline: 1.2967x; 1.0550x over previous
#include <cuda_runtime.h>
#include <cuda_bf16.h>
#include <math.h>
#include <stdint.h>

#define Bn 8
#define C1 256
#define CH 128
#define C2 256
#define Hh 80
#define Ww 80
#define HW 6400
#define NT 9
#define KT 1152
#define OC 27
#define NCHK 36   /* k3/k2 K chunks of 32, k' = n*128 + c */
#define NCHK1 8   /* k1: K=256 */
#define NCHK4 4   /* k4: K=128 */

// -------- scratch --------
__device__ float g_y1[Bn*CH*HW];     // post cv1+bn1+silu, [b][c][hw]
__device__ float g_z[Bn*CH*HW];      // post dcn+bn2+silu, [b][c][hw]
__device__ float g_off[Bn*18*HW];
__device__ float g_mask[Bn*NT*HW];
__device__ uint32_t g_dcnHi[NCHK*2048];
__device__ uint32_t g_dcnLo[NCHK*2048];
__device__ uint32_t g_w1Hi[NCHK1*2048];
__device__ uint32_t g_w1Lo[NCHK1*2048];
__device__ uint32_t g_w2Hi[2*NCHK4*2048];
__device__ uint32_t g_w2Lo[2*NCHK4*2048];
__device__ uint32_t g_owHi[NCHK*512];
__device__ uint32_t g_owLo[NCHK*512];
__device__ float g_s1[CH], g_t1[CH], g_s2[CH], g_t2[CH], g_s3[C2], g_t3[C2];

__device__ __forceinline__ float silu_f(float v) { return v / (1.f + __expf(-v)); }

__device__ __forceinline__ uint32_t pack2bf(float a, float b) {
    __nv_bfloat162 t = __floats2bfloat162_rn(a, b);
    return *(uint32_t*)&t;
}
__device__ __forceinline__ uint32_t smem_u32(const void* p) {
    uint32_t a; asm("{ .reg .u64 t; cvta.to.shared.u64 t, %1; cvt.u32.u64 %0, t; }" : "=r"(a) : "l"(p));
    return a;
}
#define LDM_X4(r0,r1,r2,r3,addr) \
    asm volatile("ldmatrix.sync.aligned.m8n8.x4.shared.b16 {%0,%1,%2,%3}, [%4];" \
        : "=r"(r0),"=r"(r1),"=r"(r2),"=r"(r3) : "r"(addr))

__device__ __forceinline__ void mma_bf16(float* c, const uint32_t* a, const uint32_t* b) {
    asm volatile(
        "mma.sync.aligned.m16n8k16.row.col.f32.bf16.bf16.f32 "
        "{%0,%1,%2,%3}, {%4,%5,%6,%7}, {%8,%9}, {%0,%1,%2,%3};"
        : "+f"(c[0]), "+f"(c[1]), "+f"(c[2]), "+f"(c[3])
        : "r"(a[0]), "r"(a[1]), "r"(a[2]), "r"(a[3]), "r"(b[0]), "r"(b[1]));
}
__device__ __forceinline__ void split_pack(float w0, float w1, uint32_t* hi, uint32_t* lo) {
    float h0 = __bfloat162float(__float2bfloat16(w0));
    float h1 = __bfloat162float(__float2bfloat16(w1));
    *hi = pack2bf(h0, h1);
    *lo = pack2bf(w0 - h0, w1 - h1);
}
__device__ __forceinline__ void cpasync16(uint32_t dst, const void* src) {
    asm volatile("cp.async.cg.shared.global [%0], [%1], 16;" :: "r"(dst), "l"(src) : "memory");
}
__device__ __forceinline__ void split_sts16(const float* acc, uint32_t dh, uint32_t dl) {
    #pragma unroll
    for (int q = 0; q < 2; q++) {
        uint32_t ph[4], pl[4];
        #pragma unroll
        for (int jj = 0; jj < 4; jj++)
            split_pack(acc[q*8 + jj*2], acc[q*8 + jj*2 + 1], &ph[jj], &pl[jj]);
        asm volatile("st.shared.v4.b32 [%0], {%1,%2,%3,%4};" ::
            "r"(dh + q*16), "r"(ph[0]), "r"(ph[1]), "r"(ph[2]), "r"(ph[3]));
        asm volatile("st.shared.v4.b32 [%0], {%1,%2,%3,%4};" ::
            "r"(dl + q*16), "r"(pl[0]), "r"(pl[1]), "r"(pl[2]), "r"(pl[3]));
    }
}
#define BAR_SYNC(id)   asm volatile("bar.sync %0, 512;"   :: "r"(id) : "memory")
#define BAR_ARRIVE(id) asm volatile("bar.arrive %0, 512;" :: "r"(id) : "memory")

// high-MLP bilinear gather for 16 channels
__device__ __forceinline__ void gather16(const float* pb, int i0, int i1, int i2, int i3,
                                         float4 wv, float* acc) {
    float l0[16], l1[16];
    #pragma unroll
    for (int jj = 0; jj < 16; jj++) l0[jj] = __ldg(pb + (size_t)jj*HW + i0);
    #pragma unroll
    for (int jj = 0; jj < 16; jj++) l1[jj] = __ldg(pb + (size_t)jj*HW + i1);
    #pragma unroll
    for (int jj = 0; jj < 16; jj++) acc[jj] = wv.x*l0[jj] + wv.y*l1[jj];
    #pragma unroll
    for (int jj = 0; jj < 16; jj++) l0[jj] = __ldg(pb + (size_t)jj*HW + i2);
    #pragma unroll
    for (int jj = 0; jj < 16; jj++) l1[jj] = __ldg(pb + (size_t)jj*HW + i3);
    #pragma unroll
    for (int jj = 0; jj < 16; jj++) acc[jj] += wv.z*l0[jj] + wv.w*l1[jj];
}

// -------- prep --------
__global__ void prep_kernel(const float* __restrict__ cv1w,
                            const float* __restrict__ bn1g, const float* __restrict__ bn1b,
                            const float* __restrict__ bn1m, const float* __restrict__ bn1v,
                            const float* __restrict__ offw, const float* __restrict__ dcnw,
                            const float* __restrict__ bn2g, const float* __restrict__ bn2b,
                            const float* __restrict__ bn2m, const float* __restrict__ bn2v,
                            const float* __restrict__ cv2w,
                            const float* __restrict__ bn3g, const float* __restrict__ bn3b,
                            const float* __restrict__ bn3m, const float* __restrict__ bn3v) {
    int idx0 = blockIdx.x * blockDim.x + threadIdx.x;
    int stride = gridDim.x * blockDim.x;
    for (int i = idx0; i < NCHK*2048; i += stride) {
        int ch = i >> 11, r = i & 2047;
        int o = r >> 4, kp = r & 15;
        int kk = ch*32 + kp*2;
        int n = kk >> 7, c = kk & 127;
        split_pack(dcnw[o*KT + c*9 + n], dcnw[o*KT + (c+1)*9 + n], &g_dcnHi[i], &g_dcnLo[i]);
    }
    for (int i = idx0; i < NCHK1*2048; i += stride) {
        int ch = i >> 11, r = i & 2047;
        int o = r >> 4, kp = r & 15;
        int c = ch*32 + kp*2;
        split_pack(cv1w[o*C1 + c], cv1w[o*C1 + c + 1], &g_w1Hi[i], &g_w1Lo[i]);
    }
    for (int i = idx0; i < 2*NCHK4*2048; i += stride) {
        int z = i >> 13, r1 = i & 8191;
        int ch = r1 >> 11, r = r1 & 2047;
        int o = r >> 4, kp = r & 15;
        int c = ch*32 + kp*2;
        split_pack(cv2w[(z*128+o)*CH + c], cv2w[(z*128+o)*CH + c + 1], &g_w2Hi[i], &g_w2Lo[i]);
    }
    for (int i = idx0; i < NCHK*512; i += stride) {
        int ch = i >> 9, r = i & 511;
        int o = r >> 4, kp = r & 15;
        int kk = ch*32 + kp*2;
        int n = kk >> 7, c = kk & 127;
        float w0 = (o < OC) ? offw[o*KT + c*9 + n] : 0.f;
        float w1 = (o < OC) ? offw[o*KT + (c+1)*9 + n] : 0.f;
        split_pack(w0, w1, &g_owHi[i], &g_owLo[i]);
    }
    for (int i = idx0; i < CH; i += stride) {
        float s = bn1g[i] * rsqrtf(bn1v[i] + 1e-5f);
        g_s1[i] = s; g_t1[i] = bn1b[i] - bn1m[i]*s;
        float s2 = bn2g[i] * rsqrtf(bn2v[i] + 1e-5f);
        g_s2[i] = s2; g_t2[i] = bn2b[i] - bn2m[i]*s2;
    }
    for (int i = idx0; i < C2; i += stride) {
        float s = bn3g[i] * rsqrtf(bn3v[i] + 1e-5f);
        g_s3[i] = s; g_t3[i] = bn3b[i] - bn3m[i]*s;
    }
}

// ======== k1: cv1 (1x1, K=256) + bn1 + silu ========
__global__ __launch_bounds__(256, 2) void k1_mma(const float* __restrict__ x) {
    __shared__ char sm[40960];
    uint32_t sb = smem_u32(sm);
    int tid = threadIdx.x;
    int lane = tid & 31;
    int wid = tid >> 5;
    int b = blockIdx.y;
    int p0 = blockIdx.x * 128;

    int warp_o = (wid >> 1) * 32;
    int warp_p = (wid & 1) * 64;
    uint32_t aoff[2], boff[4];
    #pragma unroll
    for (int f = 0; f < 2; f++)
        aoff[f] = (warp_o + f*16 + (lane & 15))*80 + (lane >> 4)*16;
    #pragma unroll
    for (int gp = 0; gp < 4; gp++)
        boff[gp] = 20480 + (warp_p + (gp*2 + (lane >> 4))*8 + (lane & 7))*80
                 + ((lane >> 3) & 1)*16;

    float c[64];
    #pragma unroll
    for (int i = 0; i < 64; i++) c[i] = 0.f;

    int px = tid & 127;
    int half = tid >> 7;
    uint32_t bsh = sb + 20480 + px*80 + half*32;
    uint32_t bsl = sb + 30720 + px*80 + half*32;
    const float* xb = x + (size_t)b * C1 * HW + p0 + px;

    for (int ch = 0; ch < NCHK1; ch++) {
        {
            const uint4* sh = (const uint4*)(g_w1Hi + ch*2048);
            const uint4* sl = (const uint4*)(g_w1Lo + ch*2048);
            #pragma unroll
            for (int r = 0; r < 2; r++) {
                int i = tid + r*256;
                uint32_t d = (i >> 2)*80 + (i & 3)*16;
                *(uint4*)(sm + d) = sh[i];
                *(uint4*)(sm + 10240 + d) = sl[i];
            }
        }
        {
            int c0 = ch*32 + half*16;
            float acc[16];
            #pragma unroll
            for (int jj = 0; jj < 16; jj++)
                acc[jj] = __ldg(xb + (size_t)(c0 + jj)*HW);
            split_sts16(acc, bsh, bsl);
        }
        __syncthreads();
        #pragma unroll
        for (int s = 0; s < 2; s++) {
            int kb = s * 32;
            uint32_t ah[8], al[8], bh[16], bl[16];
            LDM_X4(ah[0],ah[1],ah[2],ah[3], sb + aoff[0] + kb);
            LDM_X4(ah[4],ah[5],ah[6],ah[7], sb + aoff[1] + kb);
            LDM_X4(al[0],al[1],al[2],al[3], sb + aoff[0] + 10240 + kb);
            LDM_X4(al[4],al[5],al[6],al[7], sb + aoff[1] + 10240 + kb);
            #pragma unroll
            for (int gp = 0; gp < 4; gp++) {
                LDM_X4(bh[gp*4],bh[gp*4+1],bh[gp*4+2],bh[gp*4+3], sb + boff[gp] + kb);
                LDM_X4(bl[gp*4],bl[gp*4+1],bl[gp*4+2],bl[gp*4+3], sb + boff[gp] + 10240 + kb);
            }
            #pragma unroll
            for (int f = 0; f < 2; f++)
                #pragma unroll
                for (int g = 0; g < 8; g++) {
                    float* cc = &c[(f*8 + g)*4];
                    mma_bf16(cc, &ah[f*4], &bh[g*2]);
                    mma_bf16(cc, &al[f*4], &bh[g*2]);
                    mma_bf16(cc, &ah[f*4], &bl[g*2]);
                }
        }
        __syncthreads();
    }
    #pragma unroll
    for (int f = 0; f < 2; f++) {
        #pragma unroll
        for (int ho = 0; ho < 2; ho++) {
            int o = warp_o + f*16 + (lane >> 2) + ho*8;
            float s = g_s1[o], t = g_t1[o];
            float* dst = g_y1 + ((size_t)b*CH + o)*HW + p0 + warp_p + 2*(lane & 3);
            #pragma unroll
            for (int g = 0; g < 8; g++) {
                float2 r;
                r.x = silu_f(c[(f*8+g)*4 + ho*2    ]*s + t);
                r.y = silu_f(c[(f*8+g)*4 + ho*2 + 1]*s + t);
                *(float2*)(dst + g*8) = r;
            }
        }
    }
}

// ======== k2: offset conv (M=32, K=1152, tap-major) ========
__global__ __launch_bounds__(256, 2) void k2_mma(const float* __restrict__ offb) {
    __shared__ char sm[25600];
    uint32_t sb = smem_u32(sm);
    int tid = threadIdx.x;
    int lane = tid & 31;
    int wid = tid >> 5;
    int b = blockIdx.y;
    int p0 = blockIdx.x * 128;

    int warp_p = wid * 16;
    uint32_t aoff[2], boff;
    #pragma unroll
    for (int f = 0; f < 2; f++)
        aoff[f] = (f*16 + (lane & 15))*80 + (lane >> 4)*16;
    boff = 5120 + (warp_p + (lane >> 4)*8 + (lane & 7))*80 + ((lane >> 3) & 1)*16;

    float c[16];
    #pragma unroll
    for (int i = 0; i < 16; i++) c[i] = 0.f;

    int px = tid & 127;
    int half = tid >> 7;
    uint32_t bsh = sb + 5120 + px*80 + half*32;
    uint32_t bsl = sb + 15360 + px*80 + half*32;
    const float* y1b = g_y1 + (size_t)b * CH * HW;
    int p = p0 + px, h = p / 80, w = p - h*80;

    for (int ch = 0; ch < NCHK; ch++) {
        if (tid < 128) {
            const uint4* sh = (const uint4*)(g_owHi + ch*512);
            const uint4* sl = (const uint4*)(g_owLo + ch*512);
            uint32_t d = (tid >> 2)*80 + (tid & 3)*16;
            *(uint4*)(sm + d) = sh[tid];
            *(uint4*)(sm + 2560 + d) = sl[tid];
        }
        {
            int n = ch >> 2;
            int c0 = ((ch & 3) << 5) + half*16;
            int yy = h + n/3 - 1, xx = w + n%3 - 1;
            bool valid = (yy >= 0 && yy < Hh && xx >= 0 && xx < Ww);
            const float* src = y1b + (size_t)c0*HW + yy*Ww + xx;
            float acc[16];
            #pragma unroll
            for (int jj = 0; jj < 16; jj++)
                acc[jj] = valid ? __ldg(src + (size_t)jj*HW) : 0.f;
            split_sts16(acc, bsh, bsl);
        }
        __syncthreads();
        #pragma unroll
        for (int s = 0; s < 2; s++) {
            int kb = s * 32;
            uint32_t ah[8], al[8], bh[4], bl[4];
            LDM_X4(ah[0],ah[1],ah[2],ah[3], sb + aoff[0] + kb);
            LDM_X4(ah[4],ah[5],ah[6],ah[7], sb + aoff[1] + kb);
            LDM_X4(al[0],al[1],al[2],al[3], sb + aoff[0] + 2560 + kb);
            LDM_X4(al[4],al[5],al[6],al[7], sb + aoff[1] + 2560 + kb);
            LDM_X4(bh[0],bh[1],bh[2],bh[3], sb + boff + kb);
            LDM_X4(bl[0],bl[1],bl[2],bl[3], sb + boff + 10240 + kb);
            #pragma unroll
            for (int f = 0; f < 2; f++)
                #pragma unroll
                for (int g = 0; g < 2; g++) {
                    float* cc = &c[(f*2 + g)*4];
                    mma_bf16(cc, &ah[f*4], &bh[g*2]);
                    mma_bf16(cc, &al[f*4], &bh[g*2]);
                    mma_bf16(cc, &ah[f*4], &bl[g*2]);
                }
        }
        __syncthreads();
    }
    #pragma unroll
    for (int f = 0; f < 2; f++) {
        #pragma unroll
        for (int ho = 0; ho < 2; ho++) {
            int o = f*16 + (lane >> 2) + ho*8;
            if (o < OC) {
                float bias = offb[o];
                int pp = p0 + warp_p + 2*(lane & 3);
                #pragma unroll
                for (int g = 0; g < 2; g++) {
                    float v0 = c[(f*2+g)*4 + ho*2    ] + bias;
                    float v1 = c[(f*2+g)*4 + ho*2 + 1] + bias;
                    if (o < 18) {
                        float* dst = g_off + ((size_t)b*18 + o)*HW + pp + g*8;
                        *(float2*)dst = make_float2(v0, v1);
                    } else {
                        float* dst = g_mask + ((size_t)b*NT + (o-18))*HW + pp + g*8;
                        *(float2*)dst = make_float2(1.f/(1.f + __expf(-v0)),
                                                    1.f/(1.f + __expf(-v1)));
                    }
                }
            }
        }
    }
}

// ======== k3: DCNv2 warp-specialized, 4-stage, bf16 3-term ========
#define TI_OFF 0
#define TW_OFF 9216
#define STG_OFF 27648
#define STG_SZ  40960
#define NSTG 4
#define K3_SMEM (STG_OFF + NSTG*STG_SZ)   /* 191488 */

__global__ __launch_bounds__(512, 1) void k3_dcn_mma(const float* __restrict__ dcnb) {
    extern __shared__ char smem[];
    uint32_t sb = smem_u32(smem);
    int tid = threadIdx.x;
    int lane = tid & 31;
    int wid = tid >> 5;
    int b = blockIdx.y;
    int p0 = blockIdx.x * 128;

    short4* tbli = (short4*)(smem + TI_OFF);
    float4* tblw = (float4*)(smem + TW_OFF);
    const float* y1b = g_y1 + (size_t)b * CH * HW;

    for (int e = tid; e < NT*128; e += 512) {
        int n = e >> 7, pxe = e & 127;
        int p = p0 + pxe, h = p / 80, w = p - h * 80;
        float m  = g_mask[((size_t)b*NT + n)*HW + p];
        float dy = g_off[((size_t)b*18 + 2*n    )*HW + p];
        float dx = g_off[((size_t)b*18 + 2*n + 1)*HW + p];
        float py = (float)(h - 1 + n/3) + dy;
        float pxf= (float)(w - 1 + n%3) + dx;
        float y0f = floorf(py), x0f = floorf(pxf);
        float fy = py - y0f, fx = pxf - x0f;
        int y0 = (int)y0f, x0 = (int)x0f;
        int y1i = y0 + 1, x1i = x0 + 1;
        float vy0 = (y0  >= 0 && y0  < Hh) ? 1.f : 0.f;
        float vy1 = (y1i >= 0 && y1i < Hh) ? 1.f : 0.f;
        float vx0 = (x0  >= 0 && x0  < Ww) ? 1.f : 0.f;
        float vx1 = (x1i >= 0 && x1i < Ww) ? 1.f : 0.f;
        int cy0 = min(max(y0, 0), Hh-1) * Ww;
        int cy1 = min(max(y1i,0), Hh-1) * Ww;
        int cx0 = min(max(x0, 0), Ww-1);
        int cx1 = min(max(x1i,0), Ww-1);
        tbli[e] = make_short4((short)(cy0+cx0), (short)(cy0+cx1),
                              (short)(cy1+cx0), (short)(cy1+cx1));
        tblw[e] = make_float4(m*(1.f-fy)*(1.f-fx)*vy0*vx0,
                              m*(1.f-fy)*fx      *vy0*vx1,
                              m*fy*(1.f-fx)      *vy1*vx0,
                              m*fy*fx            *vy1*vx1);
    }
    __syncthreads();

    if (wid >= 8) {
        // PRODUCER
        int ptid = tid - 256;
        int px = ptid & 127;
        int half = ptid >> 7;
        uint32_t brow = px*80 + half*32;
        for (int ch = 0; ch < NCHK; ch++) {
            int s = ch & (NSTG-1);
            if (ch >= NSTG) BAR_SYNC(5 + s);
            uint32_t stg = STG_OFF + s*STG_SZ;
            {
                const uint4* sh = (const uint4*)(g_dcnHi + ch*2048);
                const uint4* sl = (const uint4*)(g_dcnLo + ch*2048);
                #pragma unroll
                for (int r = 0; r < 2; r++) {
                    int i = ptid + r*256;
                    uint32_t d = (i >> 2)*80 + (i & 3)*16;
                    cpasync16(sb + stg + d, sh + i);
                    cpasync16(sb + stg + 10240 + d, sl + i);
                }
                asm volatile("cp.async.commit_group;" ::: "memory");
            }
            {
                uint32_t bbs = stg + 20480;
                int n = ch >> 2;
                int c0 = ((ch & 3) << 5) + half*16;
                float4 wv = tblw[(n << 7) + px];
                short4 iv = tbli[(n << 7) + px];
                float acc[16];
                gather16(y1b + (size_t)c0*HW, iv.x, iv.y, iv.z, iv.w, wv, acc);
                split_sts16(acc, sb + bbs + brow, sb + bbs + 10240 + brow);
            }
            asm volatile("cp.async.wait_group 0;" ::: "memory");
            asm volatile("membar.cta;" ::: "memory");
            BAR_ARRIVE(1 + s);
        }
    } else {
        // CONSUMER
        int warp_o = (wid >> 1) * 32;
        int warp_p = (wid & 1) * 64;
        uint32_t aoffr[2], boffr[4];
        #pragma unroll
        for (int f = 0; f < 2; f++)
            aoffr[f] = (warp_o + f*16 + (lane & 15))*80 + (lane >> 4)*16;
        #pragma unroll
        for (int gp = 0; gp < 4; gp++)
            boffr[gp] = 20480 + (warp_p + (gp*2 + (lane >> 4))*8 + (lane & 7))*80
                      + ((lane >> 3) & 1)*16;

        float c[64];
        #pragma unroll
        for (int i = 0; i < 64; i++) c[i] = 0.f;

        for (int ch = 0; ch < NCHK; ch++) {
            int s = ch & (NSTG-1);
            BAR_SYNC(1 + s);
            uint32_t stg = sb + STG_OFF + s*STG_SZ;
            #pragma unroll
            for (int ks = 0; ks < 2; ks++) {
                int kb = ks * 32;
                uint32_t ah[8], al[8], bh[16], bl[16];
                LDM_X4(ah[0],ah[1],ah[2],ah[3], stg + aoffr[0] + kb);
                LDM_X4(ah[4],ah[5],ah[6],ah[7], stg + aoffr[1] + kb);
                LDM_X4(al[0],al[1],al[2],al[3], stg + aoffr[0] + 10240 + kb);
                LDM_X4(al[4],al[5],al[6],al[7], stg + aoffr[1] + 10240 + kb);
                #pragma unroll
                for (int gp = 0; gp < 4; gp++) {
                    LDM_X4(bh[gp*4],bh[gp*4+1],bh[gp*4+2],bh[gp*4+3], stg + boffr[gp] + kb);
                    LDM_X4(bl[gp*4],bl[gp*4+1],bl[gp*4+2],bl[gp*4+3], stg + boffr[gp] + 10240 + kb);
                }
                #pragma unroll
                for (int f = 0; f < 2; f++)
                    #pragma unroll
                    for (int g = 0; g < 8; g++) {
                        float* cc = &c[(f*8 + g)*4];
                        mma_bf16(cc, &ah[f*4], &bh[g*2]);
                        mma_bf16(cc, &al[f*4], &bh[g*2]);
                        mma_bf16(cc, &ah[f*4], &bl[g*2]);
                    }
            }
            BAR_ARRIVE(5 + s);
        }

        #pragma unroll
        for (int f = 0; f < 2; f++) {
            #pragma unroll
            for (int ho = 0; ho < 2; ho++) {
                int o = warp_o + f*16 + (lane >> 2) + ho*8;
                float s = g_s2[o], t = g_t2[o], bias = dcnb[o];
                float* dst = g_z + ((size_t)b*CH + o)*HW + p0 + warp_p + 2*(lane & 3);
                #pragma unroll
                for (int g = 0; g < 8; g++) {
                    float2 r;
                    r.x = silu_f((c[(f*8+g)*4 + ho*2    ] + bias)*s + t);
                    r.y = silu_f((c[(f*8+g)*4 + ho*2 + 1] + bias)*s + t);
                    *(float2*)(dst + g*8) = r;
                }
            }
        }
    }
}

// ======== k4: cv2 (1x1, K=128) + bn3 + silu + residual ========
__global__ __launch_bounds__(256, 2) void k4_mma(const float* __restrict__ x,
                                                 float* __restrict__ out) {
    __shared__ char sm[40960];
    uint32_t sb = smem_u32(sm);
    int tid = threadIdx.x;
    int lane = tid & 31;
    int wid = tid >> 5;
    int b = blockIdx.y;
    int p0 = blockIdx.x * 128;
    int z = blockIdx.z;

    int warp_o = (wid >> 1) * 32;
    int warp_p = (wid & 1) * 64;
    uint32_t aoff[2], boff[4];
    #pragma unroll
    for (int f = 0; f < 2; f++)
        aoff[f] = (warp_o + f*16 + (lane & 15))*80 + (lane >> 4)*16;
    #pragma unroll
    for (int gp = 0; gp < 4; gp++)
        boff[gp] = 20480 + (warp_p + (gp*2 + (lane >> 4))*8 + (lane & 7))*80
                 + ((lane >> 3) & 1)*16;

    float c[64];
    #pragma unroll
    for (int i = 0; i < 64; i++) c[i] = 0.f;

    int px = tid & 127;
    int half = tid >> 7;
    uint32_t bsh = sb + 20480 + px*80 + half*32;
    uint32_t bsl = sb + 30720 + px*80 + half*32;
    const float* zb = g_z + (size_t)b * CH * HW + p0 + px;

    for (int ch = 0; ch < NCHK4; ch++) {
        {
            const uint4* sh = (const uint4*)(g_w2Hi + (z*NCHK4 + ch)*2048);
            const uint4* sl = (const uint4*)(g_w2Lo + (z*NCHK4 + ch)*2048);
            #pragma unroll
            for (int r = 0; r < 2; r++) {
                int i = tid + r*256;
                uint32_t d = (i >> 2)*80 + (i & 3)*16;
                *(uint4*)(sm + d) = sh[i];
                *(uint4*)(sm + 10240 + d) = sl[i];
            }
        }
        {
            int c0 = ch*32 + half*16;
            float acc[16];
            #pragma unroll
            for (int jj = 0; jj < 16; jj++)
                acc[jj] = __ldg(zb + (size_t)(c0 + jj)*HW);
            split_sts16(acc, bsh, bsl);
        }
        __syncthreads();
        #pragma unroll
        for (int s = 0; s < 2; s++) {
            int kb = s * 32;
            uint32_t ah[8], al[8], bh[16], bl[16];
            LDM_X4(ah[0],ah[1],ah[2],ah[3], sb + aoff[0] + kb);
            LDM_X4(ah[4],ah[5],ah[6],ah[7], sb + aoff[1] + kb);
            LDM_X4(al[0],al[1],al[2],al[3], sb + aoff[0] + 10240 + kb);
            LDM_X4(al[4],al[5],al[6],al[7], sb + aoff[1] + 10240 + kb);
            #pragma unroll
            for (int gp = 0; gp < 4; gp++) {
                LDM_X4(bh[gp*4],bh[gp*4+1],bh[gp*4+2],bh[gp*4+3], sb + boff[gp] + kb);
                LDM_X4(bl[gp*4],bl[gp*4+1],bl[gp*4+2],bl[gp*4+3], sb + boff[gp] + 10240 + kb);
            }
            #pragma unroll
            for (int f = 0; f < 2; f++)
                #pragma unroll
                for (int g = 0; g < 8; g++) {
                    float* cc = &c[(f*8 + g)*4];
                    mma_bf16(cc, &ah[f*4], &bh[g*2]);
                    mma_bf16(cc, &al[f*4], &bh[g*2]);
                    mma_bf16(cc, &ah[f*4], &bl[g*2]);
                }
        }
        __syncthreads();
    }
    #pragma unroll
    for (int f = 0; f < 2; f++) {
        #pragma unroll
        for (int ho = 0; ho < 2; ho++) {
            int o = z*128 + warp_o + f*16 + (lane >> 2) + ho*8;
            float s = g_s3[o], t = g_t3[o];
            size_t base = ((size_t)b*C2 + o)*HW + p0 + warp_p + 2*(lane & 3);
            #pragma unroll
            for (int g = 0; g < 8; g++) {
                float2 xr = *(const float2*)(x + base + g*8);
                float2 r;
                r.x = silu_f(c[(f*8+g)*4 + ho*2    ]*s + t) + xr.x;
                r.y = silu_f(c[(f*8+g)*4 + ho*2 + 1]*s + t) + xr.y;
                *(float2*)(out + base + g*8) = r;
            }
        }
    }
}

extern "C" void kernel_launch(void* const* d_in, const int* in_sizes, int n_in,
                              void* d_out, int out_size) {
    const float* x     = (const float*)d_in[0];
    const float* cv1w  = (const float*)d_in[1];
    const float* bn1g  = (const float*)d_in[2];
    const float* bn1b  = (const float*)d_in[3];
    const float* bn1m  = (const float*)d_in[4];
    const float* bn1v  = (const float*)d_in[5];
    const float* offw  = (const float*)d_in[6];
    const float* offb  = (const float*)d_in[7];
    const float* dcnw  = (const float*)d_in[8];
    const float* dcnb  = (const float*)d_in[9];
    const float* bn2g  = (const float*)d_in[10];
    const float* bn2b  = (const float*)d_in[11];
    const float* bn2m  = (const float*)d_in[12];
    const float* bn2v  = (const float*)d_in[13];
    const float* cv2w  = (const float*)d_in[14];
    const float* bn3g  = (const float*)d_in[15];
    const float* bn3b  = (const float*)d_in[16];
    const float* bn3m  = (const float*)d_in[17];
    const float* bn3v  = (const float*)d_in[18];
    float* out = (float*)d_out;

    cudaFuncSetAttribute(k3_dcn_mma, cudaFuncAttributeMaxDynamicSharedMemorySize, K3_SMEM);

    prep_kernel<<<2048, 256>>>(cv1w, bn1g, bn1b, bn1m, bn1v, offw, dcnw,
                               bn2g, bn2b, bn2m, bn2v, cv2w, bn3g, bn3b, bn3m, bn3v);
    k1_mma<<<dim3(HW/128, Bn), 256>>>(x);
    k2_mma<<<dim3(HW/128, Bn), 256>>>(offb);
    k3_dcn_mma<<<dim3(HW/128, Bn), 512, K3_SMEM>>>(dcnb);
    k4_mma<<<dim3(HW/128, Bn, 2), 256>>>(x, out);
}